// round 15
// baseline (speedup 1.0000x reference)
#include <cuda_runtime.h>
#include <cuda_fp16.h>
#include <cstdint>
#include <cstddef>

// ---------------------------------------------------------------------------
// sMGU cell: B=65536, IN=256, H=512
// fp16-input mma.sync GEMM [B,768]@[768,1024] (f/c gates interleaved per
// column pair), fp32 accumulate, fused elementwise epilogue.
// R14: occupancy ladder closed (R13: 36->48% occ, zero delta). New lever is
// L1 bytes/MAC: warp tile 32x64 (0.094 B/MAC vs 0.125) at the SAME 24
// warps/SM -> CTA 128x128, 8 warps (4x2), 3 CTAs/SM, reg cap 85.
// ---------------------------------------------------------------------------

#define H_DIM   512
#define BH      33554432ull            // B*H
#define KTOT    768
#define KC      32                     // k-chunk (halves)
#define NCHUNK  24                     // 768/32
#define NSTAGE  3
#define ROWH    40                     // smem row stride in halves (pad 32->40)
#define ROWB    (ROWH * 2)             // 80 bytes
#define STG_B   ((128 + 128) * ROWB)   // bytes per stage (A + B tiles) = 20480
#define EPI_STRIDE 132                 // epilogue smem row stride (floats)
#define SMEM_BYTES (EPI_STRIDE * 128 * 4)  // 67584 >= 3*STG_B (61440)

// fp16 operands (RN-rounded once in prep).
// g_Ah[row][k]: k<256 = x[row], k>=256 = h_prev[row].
// g_Wth[n][k]:  h = n>>1, gate = n&1 (0=f, 1=c).
__device__ __half g_Ah [65536ull * KTOT];
__device__ __half g_Wth[1024 * KTOT];

// ------------------------------- helpers -----------------------------------
__device__ __forceinline__ uint32_t smem_u32(const void* p) {
    uint32_t a;
    asm("{ .reg .u64 t; cvta.to.shared.u64 t, %1; cvt.u32.u64 %0, t; }"
        : "=r"(a) : "l"(p));
    return a;
}
__device__ __forceinline__ void cp16(uint32_t dst, const void* src) {
    asm volatile("cp.async.cg.shared.global [%0], [%1], 16;"
                 :: "r"(dst), "l"(src));
}
__device__ __forceinline__ void ldm_x4(uint32_t* r, uint32_t addr) {
    asm volatile("ldmatrix.sync.aligned.m8n8.x4.shared.b16 {%0,%1,%2,%3}, [%4];"
                 : "=r"(r[0]), "=r"(r[1]), "=r"(r[2]), "=r"(r[3]) : "r"(addr));
}
__device__ __forceinline__ void mma_f16(float* d, const uint32_t* a,
                                        const uint32_t* b) {
    asm volatile(
        "mma.sync.aligned.m16n8k16.row.col.f32.f16.f16.f32 "
        "{%0,%1,%2,%3}, {%4,%5,%6,%7}, {%8,%9}, {%0,%1,%2,%3};"
        : "+f"(d[0]), "+f"(d[1]), "+f"(d[2]), "+f"(d[3])
        : "r"(a[0]), "r"(a[1]), "r"(a[2]), "r"(a[3]), "r"(b[0]), "r"(b[1]));
}

__device__ __forceinline__ float tanh_fast(float v) {
    float e = __expf(2.0f * v);
    return 1.0f - __fdividef(2.0f, e + 1.0f);
}
__device__ __forceinline__ void cell(float df, float dc, float bfe, float bce,
                                     float mpv, float cpv, float npv,
                                     float& h, float& c, float& n, float& m) {
    float a  = df + bfe + mpv;              // log f_t + m_prev
    m = fmaxf(a, 0.0f);
    float e  = __expf(-fabsf(a));           // one exp covers both branches
    float fp = (a >= 0.0f) ? 1.0f : e;      // exp(a - m)
    float ip = (a >= 0.0f) ? e : 1.0f;      // exp(-m)
    float th = tanh_fast(dc + bce);
    c = fp * cpv + ip * th;
    n = fp * npv + ip;
    h = tanh_fast(__fdividef(c, fmaxf(n, 1e-8f)));
}

// ------------------------------ merged prep --------------------------------
// blocks [0,1024): weights -> g_Wth.  blocks [1024,25600): acts -> g_Ah.
__global__ void prep_all(const float4* __restrict__ x4,
                         const float4* __restrict__ h4,
                         const float* __restrict__ wf,
                         const float* __restrict__ wc,
                         const float* __restrict__ rf,
                         const float* __restrict__ rc) {
    const int b = blockIdx.x;
    if (b < 1024) {
        int n = b, h = n >> 1, gate = n & 1;
        const float* W = gate ? wc : wf;
        const float* R = gate ? rc : rf;
        for (int k = threadIdx.x; k < KTOT; k += blockDim.x) {
            float v = (k < 256) ? W[(size_t)k * H_DIM + h]
                                : R[(size_t)(k - 256) * H_DIM + h];
            g_Wth[(size_t)n * KTOT + k] = __float2half_rn(v);
        }
        return;
    }
    size_t idx = (size_t)(b - 1024) * blockDim.x + threadIdx.x;
    size_t row = idx / 96;
    int    q   = (int)(idx % 96);       // 8-half group; k0 = q*8
    float4 a, c;
    if (q < 32) {                       // from x
        a = x4[row * 64 + q * 2];
        c = x4[row * 64 + q * 2 + 1];
    } else {                            // from h_prev
        a = h4[row * 128 + (q - 32) * 2];
        c = h4[row * 128 + (q - 32) * 2 + 1];
    }
    __half2 p0 = __float22half2_rn(make_float2(a.x, a.y));
    __half2 p1 = __float22half2_rn(make_float2(a.z, a.w));
    __half2 p2 = __float22half2_rn(make_float2(c.x, c.y));
    __half2 p3 = __float22half2_rn(make_float2(c.z, c.w));
    uint4 v;
    v.x = *reinterpret_cast<uint32_t*>(&p0);
    v.y = *reinterpret_cast<uint32_t*>(&p1);
    v.z = *reinterpret_cast<uint32_t*>(&p2);
    v.w = *reinterpret_cast<uint32_t*>(&p3);
    reinterpret_cast<uint4*>(g_Ah)[idx] = v;
}

// ------------------------------ main kernel --------------------------------
// CTA 128 rows x 128 cols. 8 warps, (wm 0..3) x (wn 0..1), warp tile 32x64.
extern "C" __global__ void __launch_bounds__(256, 3)
smgu_main(const float* __restrict__ cprev, const float* __restrict__ nprev,
          const float* __restrict__ mprev, const float* __restrict__ bfv,
          const float* __restrict__ bcv,   float* __restrict__ out) {
    extern __shared__ float smem[];
    const int tid  = threadIdx.x;
    const int lane = tid & 31, wid = tid >> 5;
    const int wm   = wid & 3,  wn  = wid >> 2;
    const int mtile = (int)blockIdx.x >> 3;
    const int ntile = (int)blockIdx.x & 7;
    const int m0  = mtile * 128;
    const int ncb = ntile * 128;

    const uint32_t sbase = smem_u32(smem);

    // loader: A 128x32h (512 cp16, 2/thr) + B 128x32h (512 cp16, 2/thr)
    const int lrow = tid >> 2, lseg = tid & 3;
    const __half* aptr = g_Ah  + (size_t)(m0  + lrow) * KTOT + lseg * 8;
    const __half* bptr = g_Wth + (size_t)(ncb + lrow) * KTOT + lseg * 8;
    const uint32_t ad = (uint32_t)(lrow * ROWB + lseg * 16);
    const uint32_t bd = (uint32_t)(128 * ROWB + lrow * ROWB + lseg * 16);
    // second half (rows +64): offset in both gmem (+64*KTOT halves) and smem
    const uint32_t rowoff_s = 64u * ROWB;
    const size_t   rowoff_g = 64u * KTOT;

    float acc[2][8][4];                  // mf x nf x frag = 64 regs
#pragma unroll
    for (int i = 0; i < 2; i++)
#pragma unroll
        for (int j = 0; j < 8; j++)
#pragma unroll
            for (int r = 0; r < 4; r++) acc[i][j][r] = 0.0f;

    auto load = [&](int s) {
        const uint32_t sb = sbase + (uint32_t)(s * STG_B);
        cp16(sb + ad,            aptr);
        cp16(sb + ad + rowoff_s, aptr + rowoff_g);
        cp16(sb + bd,            bptr);
        cp16(sb + bd + rowoff_s, bptr + rowoff_g);
        asm volatile("cp.async.commit_group;" ::: "memory");
        aptr += KC; bptr += KC;
    };

    load(0);
    load(1);

    // ldmatrix per-thread base offsets (bytes, within a stage)
    const uint32_t a_off = (uint32_t)((wm * 32 + (lane & 15)) * ROWB
                                      + (lane >> 4) * 16);
    const uint32_t b_off = (uint32_t)(128 * ROWB
                                      + (wn * 64 + ((lane >> 4) << 3)
                                         + (lane & 7)) * ROWB
                                      + ((lane >> 3) & 1) * 16);

    for (int c = 0; c < NCHUNK; c++) {
        const int s = c % NSTAGE;
        asm volatile("cp.async.wait_group 1;" ::: "memory");
        __syncthreads();   // all warps have chunk c; all done reading c-1

        if (c + 2 < NCHUNK) load((c + 2) % NSTAGE);     // stage of c-1
        else asm volatile("cp.async.commit_group;" ::: "memory");

        const uint32_t stg = sbase + (uint32_t)(s * STG_B);
        const uint32_t ab  = stg + a_off;
        const uint32_t bb  = stg + b_off;
#pragma unroll
        for (int kk = 0; kk < 2; kk++) {             // two k16 steps
            const uint32_t kb = (uint32_t)(kk * 32); // 16 halves
            uint32_t afr[2][4];
#pragma unroll
            for (int mf = 0; mf < 2; mf++)
                ldm_x4(afr[mf], ab + (uint32_t)(mf * 16 * ROWB) + kb);
#pragma unroll
            for (int p = 0; p < 4; p++) {            // stream B pairs
                uint32_t br[4];
                ldm_x4(br, bb + (uint32_t)(p * 16 * ROWB) + kb);
#pragma unroll
                for (int mf = 0; mf < 2; mf++) {
                    mma_f16(acc[mf][2 * p],     afr[mf], br);
                    mma_f16(acc[mf][2 * p + 1], afr[mf], br + 2);
                }
            }
        }
    }

    // ------------------- epilogue: stage through SMEM ---------------------
    __syncthreads();                    // all mma reads of smem done

#pragma unroll
    for (int nf = 0; nf < 8; nf++) {
        const int col = wn * 64 + nf * 8 + 2 * (lane & 3);
#pragma unroll
        for (int mf = 0; mf < 2; mf++) {
            const int row = wm * 32 + mf * 16 + (lane >> 2);
            *reinterpret_cast<float2*>(smem + row * EPI_STRIDE + col) =
                make_float2(acc[mf][nf][0], acc[mf][nf][1]);
            *reinterpret_cast<float2*>(smem + (row + 8) * EPI_STRIDE + col) =
                make_float2(acc[mf][nf][2], acc[mf][nf][3]);
        }
    }
    __syncthreads();

    float* out_h = out;
    float* out_c = out + BH;
    float* out_n = out + 2 * BH;
    float* out_m = out + 3 * BH;

    // reader: row (128 floats = 64 h) per 16 lanes; warp does 2 rows/iter;
    // 8 warps x 2 rows x 8 iters = 128 rows.
    const int ln = lane & 15;
    const int rsub = lane >> 4;
    const int hb = ntile * 64 + 4 * ln;           // global h of this 4-vector
    const float4 bf = *reinterpret_cast<const float4*>(bfv + hb);
    const float4 bc = *reinterpret_cast<const float4*>(bcv + hb);

#pragma unroll
    for (int u = 0; u < 8; u++) {
        const int r = wid * 2 + rsub + 16 * u;    // local row
        const float* sp = smem + r * EPI_STRIDE + 8 * ln;
        float4 q0 = *reinterpret_cast<const float4*>(sp);      // pf0 pc0 pf1 pc1
        float4 q1 = *reinterpret_cast<const float4*>(sp + 4);  // pf2 pc2 pf3 pc3

        const size_t g = (size_t)(m0 + r) * H_DIM + hb;
        float4 mp = *reinterpret_cast<const float4*>(mprev + g);
        float4 cp = *reinterpret_cast<const float4*>(cprev + g);
        float4 np = *reinterpret_cast<const float4*>(nprev + g);

        float4 rh, rc, rn, rm;
        cell(q0.x, q0.y, bf.x, bc.x, mp.x, cp.x, np.x, rh.x, rc.x, rn.x, rm.x);
        cell(q0.z, q0.w, bf.y, bc.y, mp.y, cp.y, np.y, rh.y, rc.y, rn.y, rm.y);
        cell(q1.x, q1.y, bf.z, bc.z, mp.z, cp.z, np.z, rh.z, rc.z, rn.z, rm.z);
        cell(q1.z, q1.w, bf.w, bc.w, mp.w, cp.w, np.w, rh.w, rc.w, rn.w, rm.w);

        *reinterpret_cast<float4*>(out_h + g) = rh;
        *reinterpret_cast<float4*>(out_c + g) = rc;
        *reinterpret_cast<float4*>(out_n + g) = rn;
        *reinterpret_cast<float4*>(out_m + g) = rm;
    }
}

// ------------------------------ launcher -----------------------------------
extern "C" void kernel_launch(void* const* d_in, const int* in_sizes, int n_in,
                              void* d_out, int out_size) {
    const float* x     = (const float*)d_in[0];
    const float* hprev = (const float*)d_in[1];
    const float* cprev = (const float*)d_in[2];
    const float* nprev = (const float*)d_in[3];
    const float* mprev = (const float*)d_in[4];
    const float* wf    = (const float*)d_in[5];
    const float* wc    = (const float*)d_in[6];
    const float* rf    = (const float*)d_in[7];
    const float* rc    = (const float*)d_in[8];
    const float* bf    = (const float*)d_in[9];
    const float* bc    = (const float*)d_in[10];

    cudaFuncSetAttribute(smgu_main,
                         cudaFuncAttributeMaxDynamicSharedMemorySize,
                         SMEM_BYTES);

    prep_all<<<25600, 256>>>((const float4*)x, (const float4*)hprev,
                             wf, wc, rf, rc);
    smgu_main<<<4096, 256, SMEM_BYTES>>>(cprev, nprev, mprev,
                                         bf, bc, (float*)d_out);
}

// round 16
// speedup vs baseline: 1.5319x; 1.5319x over previous
#include <cuda_runtime.h>
#include <cuda_fp16.h>
#include <cstdint>
#include <cstddef>

// ---------------------------------------------------------------------------
// sMGU cell: B=65536, IN=256, H=512
// fp16-input mma.sync GEMM [B,768]@[768,1024] (f/c gates interleaved per
// column pair), fp32 accumulate, fused elementwise epilogue.
// R15 = exact revert to R12, the empirical optimum of the explored design
// space: CTA 128x64, 8 warps (warp tile 32x32), 3 CTAs/SM, 3-stage cp.async
// pipeline with wait_group 1 + one barrier per chunk, SMEM-staged coalesced
// epilogue, merged single prep launch. Every perturbation tried in
// R10/R11/R13/R14 (prefetch, .cs stores, deeper pipeline, 4 CTAs/SM,
// 32x64 tiles) regressed or was neutral.
// ---------------------------------------------------------------------------

#define H_DIM   512
#define BH      33554432ull            // B*H
#define KTOT    768
#define KC      32                     // k-chunk (halves)
#define NCHUNK  24                     // 768/32
#define NSTAGE  3
#define ROWH    40                     // smem row stride in halves (pad 32->40)
#define ROWB    (ROWH * 2)             // 80 bytes
#define STG_B   ((128 + 64) * ROWB)    // bytes per stage (A + B tiles) = 15360
#define EPI_STRIDE 68                  // epilogue smem row stride (floats)
#define SMEM_BYTES (NSTAGE * STG_B)    // 46080 >= 128*68*4 (34816); 3 CTAs/SM

// fp16 operands (RN-rounded once in prep).
// g_Ah[row][k]: k<256 = x[row], k>=256 = h_prev[row].
// g_Wth[n][k]:  h = n>>1, gate = n&1 (0=f, 1=c).
__device__ __half g_Ah [65536ull * KTOT];
__device__ __half g_Wth[1024 * KTOT];

// ------------------------------- helpers -----------------------------------
__device__ __forceinline__ uint32_t smem_u32(const void* p) {
    uint32_t a;
    asm("{ .reg .u64 t; cvta.to.shared.u64 t, %1; cvt.u32.u64 %0, t; }"
        : "=r"(a) : "l"(p));
    return a;
}
__device__ __forceinline__ void cp16(uint32_t dst, const void* src) {
    asm volatile("cp.async.cg.shared.global [%0], [%1], 16;"
                 :: "r"(dst), "l"(src));
}
__device__ __forceinline__ void ldm_x4(uint32_t* r, uint32_t addr) {
    asm volatile("ldmatrix.sync.aligned.m8n8.x4.shared.b16 {%0,%1,%2,%3}, [%4];"
                 : "=r"(r[0]), "=r"(r[1]), "=r"(r[2]), "=r"(r[3]) : "r"(addr));
}
__device__ __forceinline__ void mma_f16(float* d, const uint32_t* a,
                                        const uint32_t* b) {
    asm volatile(
        "mma.sync.aligned.m16n8k16.row.col.f32.f16.f16.f32 "
        "{%0,%1,%2,%3}, {%4,%5,%6,%7}, {%8,%9}, {%0,%1,%2,%3};"
        : "+f"(d[0]), "+f"(d[1]), "+f"(d[2]), "+f"(d[3])
        : "r"(a[0]), "r"(a[1]), "r"(a[2]), "r"(a[3]), "r"(b[0]), "r"(b[1]));
}

__device__ __forceinline__ float tanh_fast(float v) {
    float e = __expf(2.0f * v);
    return 1.0f - __fdividef(2.0f, e + 1.0f);
}
__device__ __forceinline__ void cell(float df, float dc, float bfe, float bce,
                                     float mpv, float cpv, float npv,
                                     float& h, float& c, float& n, float& m) {
    float a  = df + bfe + mpv;              // log f_t + m_prev
    m = fmaxf(a, 0.0f);
    float e  = __expf(-fabsf(a));           // one exp covers both branches
    float fp = (a >= 0.0f) ? 1.0f : e;      // exp(a - m)
    float ip = (a >= 0.0f) ? e : 1.0f;      // exp(-m)
    float th = tanh_fast(dc + bce);
    c = fp * cpv + ip * th;
    n = fp * npv + ip;
    h = tanh_fast(__fdividef(c, fmaxf(n, 1e-8f)));
}

// ------------------------------ merged prep --------------------------------
// blocks [0,1024): weights -> g_Wth.  blocks [1024,25600): acts -> g_Ah.
__global__ void prep_all(const float4* __restrict__ x4,
                         const float4* __restrict__ h4,
                         const float* __restrict__ wf,
                         const float* __restrict__ wc,
                         const float* __restrict__ rf,
                         const float* __restrict__ rc) {
    const int b = blockIdx.x;
    if (b < 1024) {
        int n = b, h = n >> 1, gate = n & 1;
        const float* W = gate ? wc : wf;
        const float* R = gate ? rc : rf;
        for (int k = threadIdx.x; k < KTOT; k += blockDim.x) {
            float v = (k < 256) ? W[(size_t)k * H_DIM + h]
                                : R[(size_t)(k - 256) * H_DIM + h];
            g_Wth[(size_t)n * KTOT + k] = __float2half_rn(v);
        }
        return;
    }
    size_t idx = (size_t)(b - 1024) * blockDim.x + threadIdx.x;
    size_t row = idx / 96;
    int    q   = (int)(idx % 96);       // 8-half group; k0 = q*8
    float4 a, c;
    if (q < 32) {                       // from x
        a = x4[row * 64 + q * 2];
        c = x4[row * 64 + q * 2 + 1];
    } else {                            // from h_prev
        a = h4[row * 128 + (q - 32) * 2];
        c = h4[row * 128 + (q - 32) * 2 + 1];
    }
    __half2 p0 = __float22half2_rn(make_float2(a.x, a.y));
    __half2 p1 = __float22half2_rn(make_float2(a.z, a.w));
    __half2 p2 = __float22half2_rn(make_float2(c.x, c.y));
    __half2 p3 = __float22half2_rn(make_float2(c.z, c.w));
    uint4 v;
    v.x = *reinterpret_cast<uint32_t*>(&p0);
    v.y = *reinterpret_cast<uint32_t*>(&p1);
    v.z = *reinterpret_cast<uint32_t*>(&p2);
    v.w = *reinterpret_cast<uint32_t*>(&p3);
    reinterpret_cast<uint4*>(g_Ah)[idx] = v;
}

// ------------------------------ main kernel --------------------------------
// CTA 128 rows x 64 cols. 8 warps, (wm 0..3) x (wn 0..1), warp tile 32x32.
extern "C" __global__ void __launch_bounds__(256, 3)
smgu_main(const float* __restrict__ cprev, const float* __restrict__ nprev,
          const float* __restrict__ mprev, const float* __restrict__ bfv,
          const float* __restrict__ bcv,   float* __restrict__ out) {
    extern __shared__ float smem[];
    const int tid  = threadIdx.x;
    const int lane = tid & 31, wid = tid >> 5;
    const int wm   = wid & 3,  wn  = wid >> 2;
    const int mtile = (int)blockIdx.x >> 4;
    const int ntile = (int)blockIdx.x & 15;
    const int m0  = mtile * 128;
    const int ncb = ntile * 64;

    const uint32_t sbase = smem_u32(smem);

    // loader mapping: A 128x32h = 512 cp16 (2/thread), B 64x32h = 256 (1/thr)
    const int arow0 = tid >> 2,          aseg0 = tid & 3;          // u=0
    const int arow1 = (tid + 256) >> 2,  aseg1 = tid & 3;          // u=1
    const int brow  = tid >> 2,          bseg  = tid & 3;
    const __half* aptr0 = g_Ah  + (size_t)(m0 + arow0) * KTOT + aseg0 * 8;
    const __half* aptr1 = g_Ah  + (size_t)(m0 + arow1) * KTOT + aseg1 * 8;
    const __half* bptr  = g_Wth + (size_t)(ncb + brow) * KTOT + bseg * 8;
    const uint32_t ad0 = (uint32_t)(arow0 * ROWB + aseg0 * 16);
    const uint32_t ad1 = (uint32_t)(arow1 * ROWB + aseg1 * 16);
    const uint32_t bd  = (uint32_t)(128 * ROWB + brow * ROWB + bseg * 16);

    float acc[2][4][4];                  // mf x nf x frag = 32 regs
#pragma unroll
    for (int i = 0; i < 2; i++)
#pragma unroll
        for (int j = 0; j < 4; j++)
#pragma unroll
            for (int r = 0; r < 4; r++) acc[i][j][r] = 0.0f;

    auto load = [&](int s) {
        const uint32_t sb = sbase + (uint32_t)(s * STG_B);
        cp16(sb + ad0, aptr0);
        cp16(sb + ad1, aptr1);
        cp16(sb + bd,  bptr);
        asm volatile("cp.async.commit_group;" ::: "memory");
        aptr0 += KC; aptr1 += KC; bptr += KC;
    };

    load(0);
    load(1);

    // ldmatrix per-thread base offsets (bytes, within a stage)
    const uint32_t a_off = (uint32_t)((wm * 32 + (lane & 15)) * ROWB
                                      + (lane >> 4) * 16);
    const uint32_t b_off = (uint32_t)(128 * ROWB
                                      + (wn * 32 + ((lane >> 4) << 3)
                                         + (lane & 7)) * ROWB
                                      + ((lane >> 3) & 1) * 16);

    for (int c = 0; c < NCHUNK; c++) {
        const int s = c % NSTAGE;
        asm volatile("cp.async.wait_group 1;" ::: "memory");
        __syncthreads();   // all warps have chunk c; all done reading c-1

        if (c + 2 < NCHUNK) load((c + 2) % NSTAGE);     // stage of c-1
        else asm volatile("cp.async.commit_group;" ::: "memory");

        const uint32_t stg = sbase + (uint32_t)(s * STG_B);
        const uint32_t ab  = stg + a_off;
        const uint32_t bb  = stg + b_off;
#pragma unroll
        for (int kk = 0; kk < 2; kk++) {             // two k16 steps
            const uint32_t kb = (uint32_t)(kk * 32); // 16 halves
            uint32_t afr[2][4];
#pragma unroll
            for (int mf = 0; mf < 2; mf++)
                ldm_x4(afr[mf], ab + (uint32_t)(mf * 16 * ROWB) + kb);
#pragma unroll
            for (int p = 0; p < 2; p++) {            // stream B pairs
                uint32_t br[4];
                ldm_x4(br, bb + (uint32_t)(p * 16 * ROWB) + kb);
#pragma unroll
                for (int mf = 0; mf < 2; mf++) {
                    mma_f16(acc[mf][2 * p],     afr[mf], br);
                    mma_f16(acc[mf][2 * p + 1], afr[mf], br + 2);
                }
            }
        }
    }

    // ------------------- epilogue: stage through SMEM ---------------------
    __syncthreads();                    // all mma reads of smem done

#pragma unroll
    for (int nf = 0; nf < 4; nf++) {
        const int col = wn * 32 + nf * 8 + 2 * (lane & 3);
#pragma unroll
        for (int mf = 0; mf < 2; mf++) {
            const int row = wm * 32 + mf * 16 + (lane >> 2);
            *reinterpret_cast<float2*>(smem + row * EPI_STRIDE + col) =
                make_float2(acc[mf][nf][0], acc[mf][nf][1]);
            *reinterpret_cast<float2*>(smem + (row + 8) * EPI_STRIDE + col) =
                make_float2(acc[mf][nf][2], acc[mf][nf][3]);
        }
    }
    __syncthreads();

    float* out_h = out;
    float* out_c = out + BH;
    float* out_n = out + 2 * BH;
    float* out_m = out + 3 * BH;

    // reader: row (64 floats = 32 h) per 8 lanes; warp does 4 rows/iter;
    // 8 warps x 4 rows x 4 iters = 128 rows.
    const int ln = lane & 7;
    const int rsub = lane >> 3;                   // 0..3
    const int hb = ntile * 32 + 4 * ln;           // global h of this 4-vector
    const float4 bf = *reinterpret_cast<const float4*>(bfv + hb);
    const float4 bc = *reinterpret_cast<const float4*>(bcv + hb);

#pragma unroll
    for (int u = 0; u < 4; u++) {
        const int r = wid * 4 + rsub + 32 * u;    // local row
        const float* sp = smem + r * EPI_STRIDE + 8 * ln;
        float4 q0 = *reinterpret_cast<const float4*>(sp);      // pf0 pc0 pf1 pc1
        float4 q1 = *reinterpret_cast<const float4*>(sp + 4);  // pf2 pc2 pf3 pc3

        const size_t g = (size_t)(m0 + r) * H_DIM + hb;
        float4 mp = *reinterpret_cast<const float4*>(mprev + g);
        float4 cp = *reinterpret_cast<const float4*>(cprev + g);
        float4 np = *reinterpret_cast<const float4*>(nprev + g);

        float4 rh, rc, rn, rm;
        cell(q0.x, q0.y, bf.x, bc.x, mp.x, cp.x, np.x, rh.x, rc.x, rn.x, rm.x);
        cell(q0.z, q0.w, bf.y, bc.y, mp.y, cp.y, np.y, rh.y, rc.y, rn.y, rm.y);
        cell(q1.x, q1.y, bf.z, bc.z, mp.z, cp.z, np.z, rh.z, rc.z, rn.z, rm.z);
        cell(q1.z, q1.w, bf.w, bc.w, mp.w, cp.w, np.w, rh.w, rc.w, rn.w, rm.w);

        *reinterpret_cast<float4*>(out_h + g) = rh;
        *reinterpret_cast<float4*>(out_c + g) = rc;
        *reinterpret_cast<float4*>(out_n + g) = rn;
        *reinterpret_cast<float4*>(out_m + g) = rm;
    }
}

// ------------------------------ launcher -----------------------------------
extern "C" void kernel_launch(void* const* d_in, const int* in_sizes, int n_in,
                              void* d_out, int out_size) {
    const float* x     = (const float*)d_in[0];
    const float* hprev = (const float*)d_in[1];
    const float* cprev = (const float*)d_in[2];
    const float* nprev = (const float*)d_in[3];
    const float* mprev = (const float*)d_in[4];
    const float* wf    = (const float*)d_in[5];
    const float* wc    = (const float*)d_in[6];
    const float* rf    = (const float*)d_in[7];
    const float* rc    = (const float*)d_in[8];
    const float* bf    = (const float*)d_in[9];
    const float* bc    = (const float*)d_in[10];

    cudaFuncSetAttribute(smgu_main,
                         cudaFuncAttributeMaxDynamicSharedMemorySize,
                         SMEM_BYTES);

    prep_all<<<25600, 256>>>((const float4*)x, (const float4*)hprev,
                             wf, wc, rf, rc);
    smgu_main<<<8192, 256, SMEM_BYTES>>>(cprev, nprev, mprev,
                                         bf, bc, (float*)d_out);
}